// round 2
// baseline (speedup 1.0000x reference)
#include <cuda_runtime.h>

typedef unsigned long long u64;

// ---------------- packed f32x2 helpers ----------------
__device__ __forceinline__ u64 f2pack(float a, float b) {
    u64 r; asm("mov.b64 %0,{%1,%2};" : "=l"(r) : "f"(a), "f"(b)); return r;
}
__device__ __forceinline__ void f2unpack(u64 v, float& a, float& b) {
    asm("mov.b64 {%0,%1},%2;" : "=f"(a), "=f"(b) : "l"(v));
}
__device__ __forceinline__ u64 f2fma(u64 a, u64 b, u64 c) {
    u64 d; asm("fma.rn.f32x2 %0,%1,%2,%3;" : "=l"(d) : "l"(a), "l"(b), "l"(c)); return d;
}

// ---------------- LIF step ----------------
// i_dec=0.75, v_dec=0.96875, W_SCALE=64, THETA=5120, REF_DELAY=1 (ps = spiked last step)
__device__ __forceinline__ float lif(float x, float& u, float& v, float& ps) {
    u = __fadd_rn(__fmul_rn(0.75f, u), __fmul_rn(64.0f, x));
    float vv = (ps > 0.0f) ? 0.0f : __fadd_rn(__fmul_rn(0.96875f, v), u);
    float s  = (vv >= 5120.0f) ? 1.0f : 0.0f;
    v  = (s > 0.0f) ? 0.0f : vv;
    ps = s;
    return s;
}

// ---------------- static scratch (t-major [t][neuron]) ----------------
__device__ float g_x0[128 * 48 * 4 * 26 * 26];   // transposed input
__device__ float g_s1[128 * 48 * 8 * 24 * 24];
__device__ float g_s2[128 * 48 * 8 * 12 * 12];
__device__ float g_s3[128 * 48 * 16 * 12 * 12];
__device__ float g_s4[128 * 48 * 16 * 6 * 6];
__device__ float g_s5[128 * 48 * 32 * 6 * 6];
__device__ float g_s6[128 * 48 * 32 * 3 * 3];
__device__ float g_s7[128 * 48 * 512];
__device__ float g_w1g[288 * 512];               // fc1 weights, gathered float4 layout

// ---------------- input transpose: [n][t] -> [t][n] ----------------
__global__ void k_transpose_in(const float* __restrict__ in, float* __restrict__ out) {
    __shared__ float tile[32][33];
    const int N = 48 * 4 * 26 * 26;  // 129792
    int n0 = blockIdx.x * 32, t0 = blockIdx.y * 32;
    int tx = threadIdx.x, ty = threadIdx.y;  // block (32,8)
#pragma unroll
    for (int j = 0; j < 32; j += 8)
        tile[ty + j][tx] = in[(size_t)(n0 + ty + j) * 128 + (t0 + tx)];
    __syncthreads();
#pragma unroll
    for (int j = 0; j < 32; j += 8)
        out[(size_t)(t0 + ty + j) * N + (n0 + tx)] = tile[tx][ty + j];
}

// ---------------- fc1 weight gather: w4[(i/4)*512 + o] = {w[o][i..i+3]} ----------------
__global__ void k_prep_w1(const float* __restrict__ w, float* __restrict__ wg) {
    int e = blockIdx.x * 256 + threadIdx.x;
    if (e >= 288 * 512) return;
    int c = e & 3;
    int o = (e >> 2) & 511;
    int g = e >> 11;
    wg[e] = w[o * 288 + g * 4 + c];
}

// ---------------- fused conv + LIF + delay (2 timesteps via f32x2) ----------------
template<int IC, int IH, int IW, int OC, int K, int PAD, int OCB>
__global__ void k_conv_lif(const float* __restrict__ sin,
                           const float* __restrict__ wg,
                           float* __restrict__ sout) {
    constexpr int B = 48, T = 128;
    constexpr int OH = IH + 2 * PAD - K + 1;
    constexpr int OW = IW + 2 * PAD - K + 1;
    constexpr int NI = B * IC * IH * IW;
    constexpr int NO = B * OC * OH * OW;
    constexpr int OG = OC / OCB, POS = OH * OW, NW = IC * K * K;

    __shared__ u64 sw[OC * NW];  // [oc][ic][ky][kx] packed (w,w)
    for (int i = threadIdx.x; i < OC * NW; i += blockDim.x) {
        float wv = wg[i];
        sw[i] = f2pack(wv, wv);
    }
    __syncthreads();

    int gid = blockIdx.x * blockDim.x + threadIdx.x;
    if (gid >= B * OG * POS) return;
    int pos = gid % POS, r = gid / POS;
    int og = r % OG, b = r / OG;
    int oy = pos / OW, ox = pos % OW;
    int oc0 = og * OCB;
    int obase = (b * OC + oc0) * POS + pos;

#pragma unroll
    for (int j = 0; j < OCB; j++) sout[obase + j * POS] = 0.0f;  // delay slot 0

    float u[OCB], v[OCB], ps[OCB];
#pragma unroll
    for (int j = 0; j < OCB; j++) { u[j] = 0.0f; v[j] = 0.0f; ps[j] = 0.0f; }

    const float* ib = sin + b * IC * IH * IW;
    for (int t = 0; t < T; t += 2) {
        const float* i0 = ib + (size_t)t * NI;
        const float* i1 = i0 + NI;
        u64 acc[OCB];
#pragma unroll
        for (int j = 0; j < OCB; j++) acc[j] = 0ull;

#pragma unroll
        for (int ic = 0; ic < IC; ic++) {
#pragma unroll
            for (int ky = 0; ky < K; ky++) {
                int iy = oy + ky - PAD;
                bool vy = ((unsigned)iy < (unsigned)IH);
#pragma unroll
                for (int kx = 0; kx < K; kx++) {
                    int ix = ox + kx - PAD;
                    u64 sp = 0ull;
                    if (vy && ((unsigned)ix < (unsigned)IW)) {
                        int off = (ic * IH + iy) * IW + ix;
                        sp = f2pack(__ldg(i0 + off), __ldg(i1 + off));
                    }
                    const int widx = (ic * K + ky) * K + kx;
#pragma unroll
                    for (int j = 0; j < OCB; j++)
                        acc[j] = f2fma(sp, sw[(oc0 + j) * NW + widx], acc[j]);
                }
            }
        }
#pragma unroll
        for (int j = 0; j < OCB; j++) {
            float x0, x1;
            f2unpack(acc[j], x0, x1);
            float s0 = lif(x0, u[j], v[j], ps[j]);
            sout[(size_t)(t + 1) * NO + obase + j * POS] = s0;
            float s1 = lif(x1, u[j], v[j], ps[j]);
            if (t + 2 < T) sout[(size_t)(t + 2) * NO + obase + j * POS] = s1;
        }
    }
}

// ---------------- fused 2x2 sum-pool + LIF + delay ----------------
template<int C, int IH, int IW>
__global__ void k_pool_lif(const float* __restrict__ sin, float* __restrict__ sout) {
    constexpr int B = 48, T = 128, PH = IH / 2, PW = IW / 2;
    constexpr int NI = B * C * IH * IW;
    constexpr int NO = B * C * PH * PW;
    int n = blockIdx.x * blockDim.x + threadIdx.x;
    if (n >= NO) return;
    int px = n % PW, py = (n / PW) % PH;
    int c = (n / (PW * PH)) % C, b = n / (PW * PH * C);
    int base = ((b * C + c) * IH + 2 * py) * IW + 2 * px;
    sout[n] = 0.0f;
    float u = 0.0f, v = 0.0f, ps = 0.0f;
    for (int t = 0; t < T; t++) {
        const float* p = sin + (size_t)t * NI + base;
        float s = __fadd_rn(__fadd_rn(p[0], p[1]), __fadd_rn(p[IW], p[IW + 1]));
        float x = __fmul_rn(88.0f, s);   // POOL_W * count (exact)
        float sp = lif(x, u, v, ps);
        if (t + 1 < T) sout[(size_t)(t + 1) * NO + n] = sp;
    }
}

// ---------------- fc1 (288 -> 512) + LIF + delay ----------------
__global__ void k_fc1(const float* __restrict__ sin, const float* __restrict__ w4g,
                      float* __restrict__ sout) {
    __shared__ float sm[288];
    int b = blockIdx.x >> 2;
    int o0 = (blockIdx.x & 3) << 7;
    int tid = threadIdx.x;       // 128
    int o = o0 + tid;
    const float4* w4 = (const float4*)w4g;
    sout[b * 512 + o] = 0.0f;
    float u = 0.0f, v = 0.0f, ps = 0.0f;
    for (int t = 0; t < 128; t++) {
        for (int i = tid; i < 288; i += 128) sm[i] = sin[t * 13824 + b * 288 + i];
        __syncthreads();
        const float4* s4 = (const float4*)sm;
        float a0 = 0.0f, a1 = 0.0f, a2 = 0.0f, a3 = 0.0f;
#pragma unroll
        for (int g = 0; g < 72; g += 4) {
            float4 w_, s_;
            w_ = w4[(g + 0) * 512 + o]; s_ = s4[g + 0];
            a0 = __fmaf_rn(s_.x, w_.x, a0); a0 = __fmaf_rn(s_.y, w_.y, a0);
            a0 = __fmaf_rn(s_.z, w_.z, a0); a0 = __fmaf_rn(s_.w, w_.w, a0);
            w_ = w4[(g + 1) * 512 + o]; s_ = s4[g + 1];
            a1 = __fmaf_rn(s_.x, w_.x, a1); a1 = __fmaf_rn(s_.y, w_.y, a1);
            a1 = __fmaf_rn(s_.z, w_.z, a1); a1 = __fmaf_rn(s_.w, w_.w, a1);
            w_ = w4[(g + 2) * 512 + o]; s_ = s4[g + 2];
            a2 = __fmaf_rn(s_.x, w_.x, a2); a2 = __fmaf_rn(s_.y, w_.y, a2);
            a2 = __fmaf_rn(s_.z, w_.z, a2); a2 = __fmaf_rn(s_.w, w_.w, a2);
            w_ = w4[(g + 3) * 512 + o]; s_ = s4[g + 3];
            a3 = __fmaf_rn(s_.x, w_.x, a3); a3 = __fmaf_rn(s_.y, w_.y, a3);
            a3 = __fmaf_rn(s_.z, w_.z, a3); a3 = __fmaf_rn(s_.w, w_.w, a3);
        }
        float x = __fadd_rn(__fadd_rn(a0, a1), __fadd_rn(a2, a3));
        float sp = lif(x, u, v, ps);
        if (t + 1 < 128) sout[(t + 1) * 24576 + b * 512 + o] = sp;
        __syncthreads();
    }
}

// ---------------- fc2 (512 -> 2) + LIF + delay -> output [B][2][T] ----------------
__global__ void k_fc2(const float* __restrict__ sin, const float* __restrict__ w2,
                      float* __restrict__ out) {
    int gid = blockIdx.x;          // 96 = 48 * 2
    int b = gid >> 1, o = gid & 1;
    int lane = threadIdx.x;        // 32
    float wr[16];
#pragma unroll
    for (int k = 0; k < 16; k++) wr[k] = w2[o * 512 + lane * 16 + k];
    if (lane == 0) out[b * 256 + o * 128] = 0.0f;
    float u = 0.0f, v = 0.0f, ps = 0.0f;
    for (int t = 0; t < 128; t += 2) {
        const float* p0 = sin + t * 24576 + b * 512 + lane * 16;
        const float* p1 = p0 + 24576;
        float a0 = 0.0f, a1 = 0.0f;
#pragma unroll
        for (int k = 0; k < 16; k++) {
            a0 = __fmaf_rn(p0[k], wr[k], a0);
            a1 = __fmaf_rn(p1[k], wr[k], a1);
        }
#pragma unroll
        for (int off = 16; off > 0; off >>= 1) {
            a0 += __shfl_xor_sync(0xFFFFFFFFu, a0, off);
            a1 += __shfl_xor_sync(0xFFFFFFFFu, a1, off);
        }
        float s0 = lif(a0, u, v, ps);
        float s1 = lif(a1, u, v, ps);
        if (lane == 0) {
            out[b * 256 + o * 128 + t + 1] = s0;
            if (t + 2 < 128) out[b * 256 + o * 128 + t + 2] = s1;
        }
    }
}

// ---------------- launcher ----------------
extern "C" void kernel_launch(void* const* d_in, const int* in_sizes, int n_in,
                              void* d_out, int out_size) {
    (void)in_sizes; (void)n_in; (void)out_size;
    const float* spike_in = (const float*)d_in[0];
    const float* w1  = (const float*)d_in[1];
    const float* w2  = (const float*)d_in[2];
    const float* w3  = (const float*)d_in[3];
    const float* wf1 = (const float*)d_in[4];
    const float* wf2 = (const float*)d_in[5];
    float* out = (float*)d_out;

    void *px0, *ps1, *ps2, *ps3, *ps4, *ps5, *ps6, *ps7, *pw1g;
    cudaGetSymbolAddress(&px0, g_x0);
    cudaGetSymbolAddress(&ps1, g_s1);
    cudaGetSymbolAddress(&ps2, g_s2);
    cudaGetSymbolAddress(&ps3, g_s3);
    cudaGetSymbolAddress(&ps4, g_s4);
    cudaGetSymbolAddress(&ps5, g_s5);
    cudaGetSymbolAddress(&ps6, g_s6);
    cudaGetSymbolAddress(&ps7, g_s7);
    cudaGetSymbolAddress(&pw1g, g_w1g);

    dim3 tb(32, 8), tg(129792 / 32, 4);
    k_transpose_in<<<tg, tb>>>(spike_in, (float*)px0);
    k_prep_w1<<<(288 * 512 + 255) / 256, 256>>>(wf1, (float*)pw1g);

    // conv1: 4x26x26 -> 8x24x24 (pad 1, k5), OCB=8 -> 27648 threads
    k_conv_lif<4, 26, 26, 8, 5, 1, 8><<<27648 / 128, 128>>>((const float*)px0, w1, (float*)ps1);
    // pool1: 8x24x24 -> 8x12x12
    k_pool_lif<8, 24, 24><<<55296 / 256, 256>>>((const float*)ps1, (float*)ps2);
    // conv2: 8x12x12 -> 16x12x12 (pad 1, k3), OCB=8 -> 13824 threads
    k_conv_lif<8, 12, 12, 16, 3, 1, 8><<<13824 / 64, 64>>>((const float*)ps2, w2, (float*)ps3);
    // pool2: 16x12x12 -> 16x6x6
    k_pool_lif<16, 12, 12><<<27648 / 128, 128>>>((const float*)ps3, (float*)ps4);
    // conv3: 16x6x6 -> 32x6x6 (pad 1, k3), OCB=4 -> 13824 threads
    k_conv_lif<16, 6, 6, 32, 3, 1, 4><<<13824 / 64, 64>>>((const float*)ps4, w3, (float*)ps5);
    // pool3: 32x6x6 -> 32x3x3
    k_pool_lif<32, 6, 6><<<13824 / 64, 64>>>((const float*)ps5, (float*)ps6);
    // fc1: 288 -> 512
    k_fc1<<<192, 128>>>((const float*)ps6, (const float*)pw1g, (float*)ps7);
    // fc2: 512 -> 2, writes final delayed output [B][2][T]
    k_fc2<<<96, 32>>>((const float*)ps7, wf2, out);
}

// round 4
// speedup vs baseline: 1.0811x; 1.0811x over previous
#include <cuda_runtime.h>

typedef unsigned long long u64;

// ---------------- packed f32x2 helpers ----------------
__device__ __forceinline__ u64 f2pack(float a, float b) {
    u64 r; asm("mov.b64 %0,{%1,%2};" : "=l"(r) : "f"(a), "f"(b)); return r;
}
__device__ __forceinline__ void f2unpack(u64 v, float& a, float& b) {
    asm("mov.b64 {%0,%1},%2;" : "=f"(a), "=f"(b) : "l"(v));
}
__device__ __forceinline__ u64 f2fma(u64 a, u64 b, u64 c) {
    u64 d; asm("fma.rn.f32x2 %0,%1,%2,%3;" : "=l"(d) : "l"(a), "l"(b), "l"(c)); return d;
}

// ---------------- LIF step ----------------
// i_dec=0.75, v_dec=0.96875, W_SCALE=64, THETA=5120, REF_DELAY=1 (ps = spiked last step)
__device__ __forceinline__ float lif(float x, float& u, float& v, float& ps) {
    u = __fadd_rn(__fmul_rn(0.75f, u), __fmul_rn(64.0f, x));
    float vv = (ps > 0.0f) ? 0.0f : __fadd_rn(__fmul_rn(0.96875f, v), u);
    float s  = (vv >= 5120.0f) ? 1.0f : 0.0f;
    v  = (s > 0.0f) ? 0.0f : vv;
    ps = s;
    return s;
}

// ---------------- static scratch: pair layout u64[p][neuron], p = t/2 ----------------
__device__ u64 g_x0[64 * 48 * 4 * 26 * 26];
__device__ u64 g_s1[64 * 48 * 8 * 24 * 24];
__device__ u64 g_s2[64 * 48 * 8 * 12 * 12];
__device__ u64 g_s3[64 * 48 * 16 * 12 * 12];
__device__ u64 g_s4[64 * 48 * 16 * 6 * 6];
__device__ u64 g_s5[64 * 48 * 32 * 6 * 6];
__device__ u64 g_s6[64 * 48 * 32 * 3 * 3];
__device__ u64 g_s7[64 * 48 * 512];
__device__ float g_w1g[288 * 512];   // fc1 weights, float4-gathered [i/4][o][4]

// ---------------- input transpose: [n][t] -> pairs [p][n] ----------------
__global__ void k_transpose_in(const float* __restrict__ in, u64* __restrict__ out) {
    __shared__ float tile[128][33];
    const int N = 48 * 4 * 26 * 26;  // 129792
    int n0 = blockIdx.x * 32;
    int tx = threadIdx.x, ty = threadIdx.y;  // block (32,8)
#pragma unroll
    for (int rb = 0; rb < 4; rb++)
#pragma unroll
        for (int cb = 0; cb < 4; cb++)
            tile[32 * cb + tx][ty + 8 * rb] = in[(size_t)(n0 + ty + 8 * rb) * 128 + 32 * cb + tx];
    __syncthreads();
#pragma unroll
    for (int pb = 0; pb < 8; pb++) {
        int p = ty + 8 * pb;
        out[(size_t)p * N + n0 + tx] = f2pack(tile[2 * p][tx], tile[2 * p + 1][tx]);
    }
}

// ---------------- fc1 weight gather: wg[(i/4)*512*4 + o*4 + c] = w[o][i/4*4+c] ----------------
__global__ void k_prep_w1(const float* __restrict__ w, float* __restrict__ wg) {
    int e = blockIdx.x * 256 + threadIdx.x;
    if (e >= 288 * 512) return;
    int c = e & 3;
    int o = (e >> 2) & 511;
    int g = e >> 11;
    wg[e] = w[o * 288 + g * 4 + c];
}

// ---------------- fused conv + LIF + delay (pair layout) ----------------
template<int IC, int IH, int IW, int OC, int K, int PAD, int OCB, int BLK>
__global__ void __launch_bounds__(BLK) k_conv_lif(const u64* __restrict__ sin,
                                                  const float* __restrict__ wsrc,
                                                  u64* __restrict__ sout) {
    constexpr int B = 48;
    constexpr int OH = IH + 2 * PAD - K + 1;
    constexpr int OW = IW + 2 * PAD - K + 1;
    constexpr int NI = B * IC * IH * IW;     // u64 elems per pair-slice
    constexpr int NO = B * OC * OH * OW;
    constexpr int OG = OC / OCB, POS = OH * OW, NW = IC * K * K;

    // weights: [widx][oc], packed (w,w) so LDS.128 fetches 2 oc at once
    __shared__ __align__(16) u64 sw[NW * OC];
    for (int i = threadIdx.x; i < NW * OC; i += BLK) {
        int oc = i % OC, widx = i / OC;
        int kx = widx % K, ky = (widx / K) % K, ic = widx / (K * K);
        float wv = wsrc[(((oc * IC) + ic) * K + ky) * K + kx];
        sw[i] = f2pack(wv, wv);
    }
    __syncthreads();

    int gid = blockIdx.x * BLK + threadIdx.x;
    if (gid >= B * OG * POS) return;
    int pos = gid % POS, r = gid / POS;
    int og = r % OG, b = r / OG;
    int oy = pos / OW, ox = pos % OW;
    int oc0 = og * OCB;
    int obase = (b * OC + oc0) * POS + pos;

    float u[OCB], v[OCB], ps[OCB], cy[OCB];
#pragma unroll
    for (int j = 0; j < OCB; j++) { u[j] = 0.0f; v[j] = 0.0f; ps[j] = 0.0f; cy[j] = 0.0f; }

    const u64* ib = sin + b * IC * IH * IW;
    for (int p = 0; p < 64; p++) {
        const u64* ip = ib + (size_t)p * NI;
        u64 acc[OCB];
#pragma unroll
        for (int j = 0; j < OCB; j++) acc[j] = 0ull;

#pragma unroll 1
        for (int ic = 0; ic < IC; ic++) {
#pragma unroll
            for (int ky = 0; ky < K; ky++) {
                int iy = oy + ky - PAD;
                bool vy = ((unsigned)iy < (unsigned)IH);
#pragma unroll
                for (int kx = 0; kx < K; kx++) {
                    int ix = ox + kx - PAD;
                    u64 sp = 0ull;
                    if (vy && ((unsigned)ix < (unsigned)IW))
                        sp = __ldg(ip + (ic * IH + iy) * IW + ix);
                    int widx = (ic * K + ky) * K + kx;
                    const ulonglong2* wp =
                        reinterpret_cast<const ulonglong2*>(sw + widx * OC + oc0);
#pragma unroll
                    for (int jj = 0; jj < OCB / 2; jj++) {
                        ulonglong2 wpair = wp[jj];
                        acc[2 * jj]     = f2fma(sp, wpair.x, acc[2 * jj]);
                        acc[2 * jj + 1] = f2fma(sp, wpair.y, acc[2 * jj + 1]);
                    }
                }
            }
        }
#pragma unroll
        for (int j = 0; j < OCB; j++) {
            float x0, x1;
            f2unpack(acc[j], x0, x1);
            float s0 = lif(x0, u[j], v[j], ps[j]);
            sout[(size_t)p * NO + obase + j * POS] = f2pack(cy[j], s0);
            cy[j] = lif(x1, u[j], v[j], ps[j]);
        }
    }
}

// ---------------- fused 2x2 sum-pool + LIF + delay (pair layout) ----------------
template<int C, int IH, int IW, int BLK>
__global__ void __launch_bounds__(BLK) k_pool_lif(const u64* __restrict__ sin,
                                                  u64* __restrict__ sout) {
    constexpr int B = 48, PH = IH / 2, PW = IW / 2;
    constexpr int NI = B * C * IH * IW;
    constexpr int NO = B * C * PH * PW;
    int n = blockIdx.x * BLK + threadIdx.x;
    if (n >= NO) return;
    int px = n % PW, py = (n / PW) % PH;
    int c = (n / (PW * PH)) % C, b = n / (PW * PH * C);
    int base = ((b * C + c) * IH + 2 * py) * IW + 2 * px;
    float u = 0.0f, v = 0.0f, ps = 0.0f, cy = 0.0f;
    for (int p = 0; p < 64; p++) {
        const u64* q = sin + (size_t)p * NI + base;
        u64 e0 = __ldg(q), e1 = __ldg(q + 1), e2 = __ldg(q + IW), e3 = __ldg(q + IW + 1);
        float a0, b0, a1, b1, a2, b2, a3, b3;
        f2unpack(e0, a0, b0); f2unpack(e1, a1, b1);
        f2unpack(e2, a2, b2); f2unpack(e3, a3, b3);
        float sA = __fadd_rn(__fadd_rn(a0, a1), __fadd_rn(a2, a3));
        float sB = __fadd_rn(__fadd_rn(b0, b1), __fadd_rn(b2, b3));
        float s0 = lif(__fmul_rn(88.0f, sA), u, v, ps);
        sout[(size_t)p * NO + n] = f2pack(cy, s0);
        cy = lif(__fmul_rn(88.0f, sB), u, v, ps);
    }
}

// ---------------- fc1 (288 -> 512) + LIF + delay, t-quad ----------------
__global__ void __launch_bounds__(128) k_fc1(const u64* __restrict__ sin,
                                             const float* __restrict__ w4g,
                                             u64* __restrict__ sout) {
    __shared__ u64 sm[2][288];
    int b = blockIdx.x >> 2;
    int o = ((blockIdx.x & 3) << 7) + threadIdx.x;
    const float4* w4 = (const float4*)w4g;
    float u = 0.0f, v = 0.0f, ps = 0.0f, cy = 0.0f;
    for (int p = 0; p < 64; p += 2) {
        for (int i = threadIdx.x; i < 288; i += 128) {
            sm[0][i] = sin[(size_t)p * 13824 + b * 288 + i];
            sm[1][i] = sin[(size_t)(p + 1) * 13824 + b * 288 + i];
        }
        __syncthreads();
        u64 A[4] = {0, 0, 0, 0}, Bq[4] = {0, 0, 0, 0};
#pragma unroll 2
        for (int g = 0; g < 72; g += 4) {
#pragma unroll
            for (int gg = 0; gg < 4; gg++) {
                float4 w_ = w4[(g + gg) * 512 + o];
                u64 wx = f2pack(w_.x, w_.x), wy = f2pack(w_.y, w_.y);
                u64 wz = f2pack(w_.z, w_.z), ww = f2pack(w_.w, w_.w);
                const u64* s0 = &sm[0][(g + gg) * 4];
                const u64* s1 = &sm[1][(g + gg) * 4];
                A[gg] = f2fma(s0[0], wx, A[gg]); A[gg] = f2fma(s0[1], wy, A[gg]);
                A[gg] = f2fma(s0[2], wz, A[gg]); A[gg] = f2fma(s0[3], ww, A[gg]);
                Bq[gg] = f2fma(s1[0], wx, Bq[gg]); Bq[gg] = f2fma(s1[1], wy, Bq[gg]);
                Bq[gg] = f2fma(s1[2], wz, Bq[gg]); Bq[gg] = f2fma(s1[3], ww, Bq[gg]);
            }
        }
        float l0, h0, l1, h1, l2, h2, l3, h3;
        f2unpack(A[0], l0, h0); f2unpack(A[1], l1, h1);
        f2unpack(A[2], l2, h2); f2unpack(A[3], l3, h3);
        float xa = __fadd_rn(__fadd_rn(l0, l1), __fadd_rn(l2, l3));
        float xb = __fadd_rn(__fadd_rn(h0, h1), __fadd_rn(h2, h3));
        float s0 = lif(xa, u, v, ps);
        sout[(size_t)p * 24576 + b * 512 + o] = f2pack(cy, s0);
        cy = lif(xb, u, v, ps);
        f2unpack(Bq[0], l0, h0); f2unpack(Bq[1], l1, h1);
        f2unpack(Bq[2], l2, h2); f2unpack(Bq[3], l3, h3);
        xa = __fadd_rn(__fadd_rn(l0, l1), __fadd_rn(l2, l3));
        xb = __fadd_rn(__fadd_rn(h0, h1), __fadd_rn(h2, h3));
        s0 = lif(xa, u, v, ps);
        sout[(size_t)(p + 1) * 24576 + b * 512 + o] = f2pack(cy, s0);
        cy = lif(xb, u, v, ps);
        __syncthreads();
    }
}

// ---------------- fc2 (512 -> 2) + LIF + delay -> output [B][2][T] ----------------
__global__ void __launch_bounds__(32) k_fc2(const u64* __restrict__ sin,
                                            const float* __restrict__ w2,
                                            float* __restrict__ out) {
    int gid = blockIdx.x;          // 96 = 48 * 2
    int b = gid >> 1, o = gid & 1;
    int lane = threadIdx.x;        // 32
    float wr[16];
#pragma unroll
    for (int k = 0; k < 16; k++) wr[k] = w2[o * 512 + lane * 16 + k];
    if (lane == 0) out[b * 256 + o * 128] = 0.0f;
    float u = 0.0f, v = 0.0f, ps = 0.0f;
    for (int p = 0; p < 64; p++) {
        const u64* pp = sin + (size_t)p * 24576 + b * 512 + lane * 16;
        float a0 = 0.0f, a1 = 0.0f;
#pragma unroll
        for (int k = 0; k < 16; k++) {
            float lo, hi;
            f2unpack(__ldg(pp + k), lo, hi);
            a0 = __fmaf_rn(lo, wr[k], a0);
            a1 = __fmaf_rn(hi, wr[k], a1);
        }
#pragma unroll
        for (int off = 16; off > 0; off >>= 1) {
            a0 += __shfl_xor_sync(0xFFFFFFFFu, a0, off);
            a1 += __shfl_xor_sync(0xFFFFFFFFu, a1, off);
        }
        float s0 = lif(a0, u, v, ps);
        float s1 = lif(a1, u, v, ps);
        if (lane == 0) {
            out[b * 256 + o * 128 + 2 * p + 1] = s0;
            if (2 * p + 2 < 128) out[b * 256 + o * 128 + 2 * p + 2] = s1;
        }
    }
}

// ---------------- launcher ----------------
extern "C" void kernel_launch(void* const* d_in, const int* in_sizes, int n_in,
                              void* d_out, int out_size) {
    (void)in_sizes; (void)n_in; (void)out_size;
    const float* spike_in = (const float*)d_in[0];
    const float* w1  = (const float*)d_in[1];
    const float* w2  = (const float*)d_in[2];
    const float* w3  = (const float*)d_in[3];
    const float* wf1 = (const float*)d_in[4];
    const float* wf2 = (const float*)d_in[5];
    float* out = (float*)d_out;

    void *px0, *ps1, *ps2, *ps3, *ps4, *ps5, *ps6, *ps7, *pw1g;
    cudaGetSymbolAddress(&px0, g_x0);
    cudaGetSymbolAddress(&ps1, g_s1);
    cudaGetSymbolAddress(&ps2, g_s2);
    cudaGetSymbolAddress(&ps3, g_s3);
    cudaGetSymbolAddress(&ps4, g_s4);
    cudaGetSymbolAddress(&ps5, g_s5);
    cudaGetSymbolAddress(&ps6, g_s6);
    cudaGetSymbolAddress(&ps7, g_s7);
    cudaGetSymbolAddress(&pw1g, g_w1g);

    dim3 tb(32, 8);
    k_transpose_in<<<129792 / 32, tb>>>(spike_in, (u64*)px0);
    k_prep_w1<<<(288 * 512 + 255) / 256, 256>>>(wf1, (float*)pw1g);

    // conv1: 4x26x26 -> 8x24x24 (k5 pad1), OCB=8 -> 27648 threads
    k_conv_lif<4, 26, 26, 8, 5, 1, 8, 96><<<288, 96>>>((const u64*)px0, w1, (u64*)ps1);
    // pool1: 8x24x24 -> 8x12x12
    k_pool_lif<8, 24, 24, 256><<<216, 256>>>((const u64*)ps1, (u64*)ps2);
    // conv2: 8x12x12 -> 16x12x12 (k3 pad1), OCB=4 -> 27648 threads
    k_conv_lif<8, 12, 12, 16, 3, 1, 4, 96><<<288, 96>>>((const u64*)ps2, w2, (u64*)ps3);
    // pool2: 16x12x12 -> 16x6x6
    k_pool_lif<16, 12, 12, 128><<<216, 128>>>((const u64*)ps3, (u64*)ps4);
    // conv3: 16x6x6 -> 32x6x6 (k3 pad1), OCB=4 -> 13824 threads
    k_conv_lif<16, 6, 6, 32, 3, 1, 4, 64><<<216, 64>>>((const u64*)ps4, w3, (u64*)ps5);
    // pool3: 32x6x6 -> 32x3x3
    k_pool_lif<32, 6, 6, 64><<<216, 64>>>((const u64*)ps5, (u64*)ps6);
    // fc1: 288 -> 512
    k_fc1<<<192, 128>>>((const u64*)ps6, (const float*)pw1g, (u64*)ps7);
    // fc2: 512 -> 2, writes final delayed output [B][2][T]
    k_fc2<<<96, 32>>>((const u64*)ps7, wf2, out);
}

// round 5
// speedup vs baseline: 3.6502x; 3.3765x over previous
#include <cuda_runtime.h>

typedef unsigned long long u64;

// ---------------- packed f32x2 helpers ----------------
__device__ __forceinline__ u64 f2pack(float a, float b) {
    u64 r; asm("mov.b64 %0,{%1,%2};" : "=l"(r) : "f"(a), "f"(b)); return r;
}
__device__ __forceinline__ void f2unpack(u64 v, float& a, float& b) {
    asm("mov.b64 {%0,%1},%2;" : "=f"(a), "=f"(b) : "l"(v));
}
__device__ __forceinline__ u64 f2fma(u64 a, u64 b, u64 c) {
    u64 d; asm("fma.rn.f32x2 %0,%1,%2,%3;" : "=l"(d) : "l"(a), "l"(b), "l"(c)); return d;
}

// ---------------- LIF step ----------------
// i_dec=0.75, v_dec=0.96875, W_SCALE=64, THETA=5120, REF_DELAY=1 (ps = spiked last step)
__device__ __forceinline__ float lif(float x, float& u, float& v, float& ps) {
    u = __fadd_rn(__fmul_rn(0.75f, u), __fmul_rn(64.0f, x));
    float vv = (ps > 0.0f) ? 0.0f : __fadd_rn(__fmul_rn(0.96875f, v), u);
    float s  = (vv >= 5120.0f) ? 1.0f : 0.0f;
    v  = (s > 0.0f) ? 0.0f : vv;
    ps = s;
    return s;
}

// ---------------- static scratch: pair layout u64[p][neuron], p = t/2 ----------------
__device__ u64 g_x0[64 * 48 * 4 * 26 * 26];     // transposed input spikes
__device__ u64 g_s1[64 * 48 * 8 * 24 * 24];     // conv1 wsum
__device__ u64 g_s2[64 * 48 * 8 * 12 * 12];     // pooled spikes 1
__device__ u64 g_s3[64 * 48 * 16 * 12 * 12];    // conv2 wsum
__device__ u64 g_s4[64 * 48 * 16 * 6 * 6];      // pooled spikes 2
__device__ u64 g_s5[64 * 48 * 32 * 6 * 6];      // conv3 wsum
__device__ u64 g_s6[64 * 48 * 32 * 3 * 3];      // pooled spikes 3
__device__ u64 g_s7[64 * 48 * 512];             // fc1 wsum
__device__ u64 g_s8[64 * 48 * 512];             // fc1 spikes (delayed)
__device__ float g_w1g[288 * 512];              // fc1 weights, float4-gathered

// ---------------- input transpose: [n][t] -> pairs [p][n] ----------------
__global__ void k_transpose_in(const float* __restrict__ in, u64* __restrict__ out) {
    __shared__ float tile[128][33];
    const int N = 48 * 4 * 26 * 26;  // 129792
    int n0 = blockIdx.x * 32;
    int tx = threadIdx.x, ty = threadIdx.y;  // block (32,8)
#pragma unroll
    for (int rb = 0; rb < 4; rb++)
#pragma unroll
        for (int cb = 0; cb < 4; cb++)
            tile[32 * cb + tx][ty + 8 * rb] = in[(size_t)(n0 + ty + 8 * rb) * 128 + 32 * cb + tx];
    __syncthreads();
#pragma unroll
    for (int pb = 0; pb < 8; pb++) {
        int p = ty + 8 * pb;
        out[(size_t)p * N + n0 + tx] = f2pack(tile[2 * p][tx], tile[2 * p + 1][tx]);
    }
}

// ---------------- fc1 weight gather: wg[(i/4)*2048 + o*4 + c] = w[o][(i/4)*4+c] ----------------
__global__ void k_prep_w1(const float* __restrict__ w, float* __restrict__ wg) {
    int e = blockIdx.x * 256 + threadIdx.x;
    if (e >= 288 * 512) return;
    int c = e & 3;
    int o = (e >> 2) & 511;
    int g = e >> 11;
    wg[e] = w[o * 288 + g * 4 + c];
}

// ---------------- conv wsum: fully parallel over time (2 pairs / thread) ----------------
template<int IC, int IH, int IW, int OC, int K, int PAD, int OCB, int BPB, int BLK>
__global__ void __launch_bounds__(BLK) k_conv_wsum(const u64* __restrict__ sin,
                                                   const float* __restrict__ wsrc,
                                                   u64* __restrict__ wout) {
    constexpr int OH = IH + 2 * PAD - K + 1;
    constexpr int OW = IW + 2 * PAD - K + 1;
    constexpr int NI = 48 * IC * IH * IW;   // u64 per pair-slice
    constexpr int NO = 48 * OC * OH * OW;
    constexpr int OG = OC / OCB, POS = OH * OW, NW = IC * K * K;
    static_assert(BLK == BPB * OG * POS, "block mapping");

    __shared__ __align__(16) u64 sw[NW * OC];   // [widx][oc] packed (w,w)
    for (int i = threadIdx.x; i < NW * OC; i += BLK) {
        int oc = i % OC, widx = i / OC;
        int kx = widx % K, ky = (widx / K) % K, ic = widx / (K * K);
        float wv = wsrc[(((oc * IC) + ic) * K + ky) * K + kx];
        sw[i] = f2pack(wv, wv);
    }
    __syncthreads();

    int tid = threadIdx.x;
    int bo = tid / (OG * POS);
    int r  = tid % (OG * POS);
    int og = r / POS, pos = r % POS;
    int b  = blockIdx.x * BPB + bo;
    int p2 = blockIdx.y;                     // pair-pair index: pairs 2*p2, 2*p2+1
    int oy = pos / OW, ox = pos % OW;
    int oc0 = og * OCB;

    const u64* ip0 = sin + (size_t)(2 * p2) * NI + b * IC * IH * IW;
    const u64* ip1 = ip0 + NI;

    u64 a0[OCB], a1[OCB];
#pragma unroll
    for (int j = 0; j < OCB; j++) { a0[j] = 0ull; a1[j] = 0ull; }

#pragma unroll 1
    for (int ic = 0; ic < IC; ic++) {
#pragma unroll
        for (int ky = 0; ky < K; ky++) {
            int iy = oy + ky - PAD;
            bool vy = ((unsigned)iy < (unsigned)IH);
#pragma unroll
            for (int kx = 0; kx < K; kx++) {
                int ix = ox + kx - PAD;
                u64 sp0 = 0ull, sp1 = 0ull;
                if (vy && ((unsigned)ix < (unsigned)IW)) {
                    int off = (ic * IH + iy) * IW + ix;
                    sp0 = __ldg(ip0 + off);
                    sp1 = __ldg(ip1 + off);
                }
                int widx = (ic * K + ky) * K + kx;
                const ulonglong2* wp =
                    reinterpret_cast<const ulonglong2*>(sw + widx * OC + oc0);
#pragma unroll
                for (int jj = 0; jj < OCB / 2; jj++) {
                    ulonglong2 wpair = wp[jj];
                    a0[2 * jj]     = f2fma(sp0, wpair.x, a0[2 * jj]);
                    a0[2 * jj + 1] = f2fma(sp0, wpair.y, a0[2 * jj + 1]);
                    a1[2 * jj]     = f2fma(sp1, wpair.x, a1[2 * jj]);
                    a1[2 * jj + 1] = f2fma(sp1, wpair.y, a1[2 * jj + 1]);
                }
            }
        }
    }
    int obase = (b * OC + oc0) * POS + pos;
#pragma unroll
    for (int j = 0; j < OCB; j++) {
        wout[(size_t)(2 * p2) * NO + obase + j * POS]     = a0[j];
        wout[(size_t)(2 * p2 + 1) * NO + obase + j * POS] = a1[j];
    }
}

// ------- fused scan: conv-LIF + delay + 2x2 sum-pool + pool-LIF + delay -------
template<int C, int IH, int IW, int BLK>
__global__ void __launch_bounds__(BLK) k_scan_pool(const u64* __restrict__ wsum,
                                                   u64* __restrict__ sout) {
    constexpr int B = 48, PH = IH / 2, PW = IW / 2;
    constexpr int NC = B * C * IH * IW;   // conv neurons per pair-slice
    constexpr int NP = B * C * PH * PW;   // pooled neurons
    int n = blockIdx.x * BLK + threadIdx.x;
    if (n >= NP) return;
    int px = n % PW, py = (n / PW) % PH;
    int c = (n / (PW * PH)) % C, b = n / (PW * PH * C);
    int base = ((b * C + c) * IH + 2 * py) * IW + 2 * px;

    float uc[4], vc[4], pc[4], cs[4];
#pragma unroll
    for (int j = 0; j < 4; j++) { uc[j] = 0.0f; vc[j] = 0.0f; pc[j] = 0.0f; cs[j] = 0.0f; }
    float up = 0.0f, vp = 0.0f, pp = 0.0f, cy = 0.0f;

    for (int p = 0; p < 64; p++) {
        const u64* q = wsum + (size_t)p * NC + base;
        u64 e0 = __ldg(q), e1 = __ldg(q + 1), e2 = __ldg(q + IW), e3 = __ldg(q + IW + 1);
        float xa[4], xb[4];
        f2unpack(e0, xa[0], xb[0]); f2unpack(e1, xa[1], xb[1]);
        f2unpack(e2, xa[2], xb[2]); f2unpack(e3, xa[3], xb[3]);

        // t = 2p: pool consumes delayed conv spikes (cs = spikes at t-1)
        float sA = __fadd_rn(__fadd_rn(cs[0], cs[1]), __fadd_rn(cs[2], cs[3]));
        float spA = lif(__fmul_rn(88.0f, sA), up, vp, pp);
#pragma unroll
        for (int j = 0; j < 4; j++) cs[j] = lif(xa[j], uc[j], vc[j], pc[j]);

        // t = 2p+1
        float sB = __fadd_rn(__fadd_rn(cs[0], cs[1]), __fadd_rn(cs[2], cs[3]));
        float spB = lif(__fmul_rn(88.0f, sB), up, vp, pp);
#pragma unroll
        for (int j = 0; j < 4; j++) cs[j] = lif(xb[j], uc[j], vc[j], pc[j]);

        sout[(size_t)p * NP + n] = f2pack(cy, spA);   // pool output delayed by 1
        cy = spB;
    }
}

// ---------------- fc1 wsum: t-parallel GEMM (288 -> 512), 8 batches / block ----------------
__global__ void __launch_bounds__(512) k_fc1_wsum(const u64* __restrict__ sin,
                                                  const float* __restrict__ w4g,
                                                  u64* __restrict__ wout) {
    __shared__ __align__(16) u64 sm[8 * 288];
    int p = blockIdx.y;
    int b0 = blockIdx.x * 8;
    int o = threadIdx.x;
    for (int i = threadIdx.x; i < 8 * 288; i += 512)
        sm[i] = sin[(size_t)p * 13824 + b0 * 288 + i];
    __syncthreads();

    const float4* w4 = (const float4*)w4g;
    u64 acc[8];
#pragma unroll
    for (int bb = 0; bb < 8; bb++) acc[bb] = 0ull;

#pragma unroll 4
    for (int g = 0; g < 72; g++) {
        float4 w_ = w4[g * 512 + o];
        u64 wx = f2pack(w_.x, w_.x), wy = f2pack(w_.y, w_.y);
        u64 wz = f2pack(w_.z, w_.z), ww = f2pack(w_.w, w_.w);
#pragma unroll
        for (int bb = 0; bb < 8; bb++) {
            const ulonglong2* s = reinterpret_cast<const ulonglong2*>(sm + bb * 288 + g * 4);
            ulonglong2 s01 = s[0], s23 = s[1];
            acc[bb] = f2fma(s01.x, wx, acc[bb]);
            acc[bb] = f2fma(s01.y, wy, acc[bb]);
            acc[bb] = f2fma(s23.x, wz, acc[bb]);
            acc[bb] = f2fma(s23.y, ww, acc[bb]);
        }
    }
#pragma unroll
    for (int bb = 0; bb < 8; bb++)
        wout[(size_t)p * 24576 + (b0 + bb) * 512 + o] = acc[bb];
}

// ---------------- fc1 scan: LIF + delay over wsum ----------------
__global__ void __launch_bounds__(256) k_fc1_scan(const u64* __restrict__ w,
                                                  u64* __restrict__ s) {
    int n = blockIdx.x * 256 + threadIdx.x;   // 24576
    float u = 0.0f, v = 0.0f, ps = 0.0f, cy = 0.0f;
    for (int p = 0; p < 64; p++) {
        float x0, x1;
        f2unpack(__ldg(w + (size_t)p * 24576 + n), x0, x1);
        float s0 = lif(x0, u, v, ps);
        s[(size_t)p * 24576 + n] = f2pack(cy, s0);
        cy = lif(x1, u, v, ps);
    }
}

// ---------------- fc2 (512 -> 2) + LIF + delay -> output [B][2][T] ----------------
__global__ void __launch_bounds__(32) k_fc2(const u64* __restrict__ sin,
                                            const float* __restrict__ w2,
                                            float* __restrict__ out) {
    int gid = blockIdx.x;          // 96 = 48 * 2
    int b = gid >> 1, o = gid & 1;
    int lane = threadIdx.x;        // 32
    float wr[16];
#pragma unroll
    for (int k = 0; k < 16; k++) wr[k] = w2[o * 512 + lane * 16 + k];
    if (lane == 0) out[b * 256 + o * 128] = 0.0f;
    float u = 0.0f, v = 0.0f, ps = 0.0f;
    for (int p = 0; p < 64; p++) {
        const u64* pp = sin + (size_t)p * 24576 + b * 512 + lane * 16;
        float a0 = 0.0f, a1 = 0.0f;
#pragma unroll
        for (int k = 0; k < 16; k++) {
            float lo, hi;
            f2unpack(__ldg(pp + k), lo, hi);
            a0 = __fmaf_rn(lo, wr[k], a0);
            a1 = __fmaf_rn(hi, wr[k], a1);
        }
#pragma unroll
        for (int off = 16; off > 0; off >>= 1) {
            a0 += __shfl_xor_sync(0xFFFFFFFFu, a0, off);
            a1 += __shfl_xor_sync(0xFFFFFFFFu, a1, off);
        }
        float s0 = lif(a0, u, v, ps);
        float s1 = lif(a1, u, v, ps);
        if (lane == 0) {
            out[b * 256 + o * 128 + 2 * p + 1] = s0;
            if (2 * p + 2 < 128) out[b * 256 + o * 128 + 2 * p + 2] = s1;
        }
    }
}

// ---------------- launcher ----------------
extern "C" void kernel_launch(void* const* d_in, const int* in_sizes, int n_in,
                              void* d_out, int out_size) {
    (void)in_sizes; (void)n_in; (void)out_size;
    const float* spike_in = (const float*)d_in[0];
    const float* w1  = (const float*)d_in[1];
    const float* w2  = (const float*)d_in[2];
    const float* w3  = (const float*)d_in[3];
    const float* wf1 = (const float*)d_in[4];
    const float* wf2 = (const float*)d_in[5];
    float* out = (float*)d_out;

    void *px0, *ps1, *ps2, *ps3, *ps4, *ps5, *ps6, *ps7, *ps8, *pw1g;
    cudaGetSymbolAddress(&px0, g_x0);
    cudaGetSymbolAddress(&ps1, g_s1);
    cudaGetSymbolAddress(&ps2, g_s2);
    cudaGetSymbolAddress(&ps3, g_s3);
    cudaGetSymbolAddress(&ps4, g_s4);
    cudaGetSymbolAddress(&ps5, g_s5);
    cudaGetSymbolAddress(&ps6, g_s6);
    cudaGetSymbolAddress(&ps7, g_s7);
    cudaGetSymbolAddress(&ps8, g_s8);
    cudaGetSymbolAddress(&pw1g, g_w1g);

    dim3 tb(32, 8);
    k_transpose_in<<<129792 / 32, tb>>>(spike_in, (u64*)px0);
    k_prep_w1<<<(288 * 512 + 255) / 256, 256>>>(wf1, (float*)pw1g);

    // conv1 wsum: 4x26x26 -> 8x24x24 (k5 pad1), 1536 blocks x 576
    k_conv_wsum<4, 26, 26, 8, 5, 1, 8, 1, 576><<<dim3(48, 32), 576>>>((const u64*)px0, w1, (u64*)ps1);
    // scan1: conv1 LIF + pool 24->12 + LIF
    k_scan_pool<8, 24, 24, 256><<<216, 256>>>((const u64*)ps1, (u64*)ps2);
    // conv2 wsum: 8x12x12 -> 16x12x12
    k_conv_wsum<8, 12, 12, 16, 3, 1, 8, 1, 288><<<dim3(48, 32), 288>>>((const u64*)ps2, w2, (u64*)ps3);
    // scan2: conv2 LIF + pool 12->6 + LIF
    k_scan_pool<16, 12, 12, 128><<<216, 128>>>((const u64*)ps3, (u64*)ps4);
    // conv3 wsum: 16x6x6 -> 32x6x6
    k_conv_wsum<16, 6, 6, 32, 3, 1, 8, 2, 288><<<dim3(24, 32), 288>>>((const u64*)ps4, w3, (u64*)ps5);
    // scan3: conv3 LIF + pool 6->3 + LIF
    k_scan_pool<32, 6, 6, 64><<<216, 64>>>((const u64*)ps5, (u64*)ps6);
    // fc1 wsum GEMM + scan
    k_fc1_wsum<<<dim3(6, 64), 512>>>((const u64*)ps6, (const float*)pw1g, (u64*)ps7);
    k_fc1_scan<<<96, 256>>>((const u64*)ps7, (u64*)ps8);
    // fc2 -> output [B][2][T]
    k_fc2<<<96, 32>>>((const u64*)ps8, wf2, out);
}